// round 1
// baseline (speedup 1.0000x reference)
#include <cuda_runtime.h>
#include <math.h>

#define S_    2048        // B*A
#define N_    121
#define H_    128
#define HEADS_ 4
#define HD_   32
#define OUT_  256
#define NH_   (N_*H_)     // 15488
#define SN_   (S_*N_)     // 247808
#define KSPLIT 16
#define EPS_  1e-5f

// ---------------- scratch (device globals; no allocations allowed) ----------
__device__ float g_X[SN_*H_];          // activations [S][N][H]
__device__ float g_QKV[SN_*384];       // qkv per layer
__device__ float g_ATT[SN_*H_];        // attention output
__device__ float g_H1[SN_*H_];         // ff intermediate
__device__ float g_WTQKV[2*128*384];   // transposed weights [K][N]
__device__ float g_WTPROJ[2*128*128];
__device__ float g_WTFF1[2*128*128];
__device__ float g_WTFF2[2*128*128];
__device__ float g_WTOUT[NH_*OUT_];    // [15488][256]
__device__ float g_YP[KSPLIT*S_*OUT_]; // split-K partials

// ---------------- transpose: w[rows][cols] -> wt[cols][rows] ----------------
__global__ void k_transpose(const float* __restrict__ w, float* __restrict__ wt,
                            int rows, int cols) {
    int idx = blockIdx.x * blockDim.x + threadIdx.x;
    if (idx < rows * cols) {
        int r = idx / cols, c = idx % cols;
        wt[(size_t)c * rows + r] = w[idx];
    }
}

// ---------------- embed + tree PE + permutation -----------------------------
// grid (N_, S_), 128 threads. x[s][i][h] = forest[s][perm[i]]@w_in.T + b_in + pe
__global__ void k_embed(const float* __restrict__ forest, const int* __restrict__ adj,
                        const int* __restrict__ perm, const float* __restrict__ w_in,
                        const float* __restrict__ b_in, float* __restrict__ X) {
    int i = blockIdx.x;          // permuted position
    int s = blockIdx.y;          // sequence
    int h = threadIdx.x;
    int n = perm[i];             // original node index

    // tree positional encoding: walk to root, set bit (l-1)*3+branch per edge
    unsigned mask = 0;
    int cur = n;
    #pragma unroll 4
    for (int it = 0; it < 4; it++) {
        if (cur > 0) {
            int l = (cur < 4) ? 1 : (cur < 13) ? 2 : (cur < 40) ? 3 : 4;
            const int* e = adj + ((size_t)s * (N_ - 1) + (cur - 1)) * 3;
            mask |= 1u << ((l - 1) * 3 + e[2]);
            cur = e[0];
        }
    }

    const float* f = forest + ((size_t)s * N_ + n) * 12;
    float acc = b_in[h];
    #pragma unroll
    for (int k = 0; k < 12; k++) acc += f[k] * w_in[h * 12 + k];
    if (h < 12 && ((mask >> h) & 1u)) acc += 1.0f;
    X[((size_t)s * N_ + i) * H_ + h] = acc;
}

// ---------------- generic 16-row GEMM with fused epilogues ------------------
// Block: 128 threads = (cx 0..31) x (ry 0..3). Computes rows [m0,m0+16) x all
// Ncols = NG*128 columns. wT layout [K][Ncols]. MODE: 0 plain(+bias), 1 relu,
// 2 residual + LayerNorm (Ncols must be 128).
template<int NG, int MODE>
__global__ void k_gemm16(const float* __restrict__ A, const float* __restrict__ wT,
                         const float* __restrict__ bias, const float* __restrict__ resid,
                         const float* __restrict__ lng, const float* __restrict__ lnb,
                         float* __restrict__ out, int K, int Ncols, int ktiles,
                         int splitStride) {
    __shared__ float As[16][128];
    __shared__ float2 s_stats[16];

    int m0  = blockIdx.x * 16;
    int tid = threadIdx.x;
    int cx  = tid & 31;
    int ry  = tid >> 5;

    int t0 = (int)((size_t)blockIdx.y * ktiles / gridDim.y);
    int t1 = (int)((size_t)(blockIdx.y + 1) * ktiles / gridDim.y);
    float* o = out + (size_t)blockIdx.y * splitStride;

    float acc[NG][4][4];
    #pragma unroll
    for (int cg = 0; cg < NG; cg++)
        #pragma unroll
        for (int r = 0; r < 4; r++)
            #pragma unroll
            for (int j = 0; j < 4; j++) acc[cg][r][j] = 0.f;

    for (int t = t0; t < t1; t++) {
        __syncthreads();
        #pragma unroll
        for (int j = 0; j < 16; j++)
            As[j][tid] = A[(size_t)(m0 + j) * K + t * 128 + tid];
        __syncthreads();

        #pragma unroll 4
        for (int kk = 0; kk < 128; kk++) {
            float a[4];
            #pragma unroll
            for (int r = 0; r < 4; r++) a[r] = As[ry * 4 + r][kk];  // broadcast
            #pragma unroll
            for (int cg = 0; cg < NG; cg++) {
                const float4 w = *(const float4*)(wT + (size_t)(t * 128 + kk) * Ncols
                                                  + cg * 128 + cx * 4);
                #pragma unroll
                for (int r = 0; r < 4; r++) {
                    acc[cg][r][0] += a[r] * w.x;
                    acc[cg][r][1] += a[r] * w.y;
                    acc[cg][r][2] += a[r] * w.z;
                    acc[cg][r][3] += a[r] * w.w;
                }
            }
        }
    }

    if (MODE == 0 || MODE == 1) {
        #pragma unroll
        for (int cg = 0; cg < NG; cg++)
            #pragma unroll
            for (int r = 0; r < 4; r++) {
                int row  = m0 + ry * 4 + r;
                int col0 = cg * 128 + cx * 4;
                float4 v;
                v.x = acc[cg][r][0] + (bias ? bias[col0 + 0] : 0.f);
                v.y = acc[cg][r][1] + (bias ? bias[col0 + 1] : 0.f);
                v.z = acc[cg][r][2] + (bias ? bias[col0 + 2] : 0.f);
                v.w = acc[cg][r][3] + (bias ? bias[col0 + 3] : 0.f);
                if (MODE == 1) {
                    v.x = fmaxf(v.x, 0.f); v.y = fmaxf(v.y, 0.f);
                    v.z = fmaxf(v.z, 0.f); v.w = fmaxf(v.w, 0.f);
                }
                *(float4*)(o + (size_t)row * Ncols + col0) = v;
            }
    } else {
        // residual + LayerNorm epilogue (Ncols == 128, NG == 1)
        __syncthreads();
        #pragma unroll
        for (int r = 0; r < 4; r++) {
            int row  = ry * 4 + r;
            int col0 = cx * 4;
            const float4 rr = *(const float4*)(resid + (size_t)(m0 + row) * 128 + col0);
            As[row][col0 + 0] = acc[0][r][0] + bias[col0 + 0] + rr.x;
            As[row][col0 + 1] = acc[0][r][1] + bias[col0 + 1] + rr.y;
            As[row][col0 + 2] = acc[0][r][2] + bias[col0 + 2] + rr.z;
            As[row][col0 + 3] = acc[0][r][3] + bias[col0 + 3] + rr.w;
        }
        __syncthreads();
        // each warp (ry) reduces its own 4 rows
        #pragma unroll
        for (int rr2 = 0; rr2 < 4; rr2++) {
            int row = ry * 4 + rr2;
            float v0 = As[row][cx], v1 = As[row][cx + 32];
            float v2 = As[row][cx + 64], v3 = As[row][cx + 96];
            float sm = v0 + v1 + v2 + v3;
            float sq = v0 * v0 + v1 * v1 + v2 * v2 + v3 * v3;
            #pragma unroll
            for (int off = 16; off > 0; off >>= 1) {
                sm += __shfl_xor_sync(0xffffffffu, sm, off);
                sq += __shfl_xor_sync(0xffffffffu, sq, off);
            }
            if (cx == 0) {
                float mean = sm * (1.f / 128.f);
                float var  = sq * (1.f / 128.f) - mean * mean;
                s_stats[row] = make_float2(mean, rsqrtf(var + EPS_));
            }
        }
        __syncthreads();
        #pragma unroll
        for (int r = 0; r < 4; r++) {
            int row = ry * 4 + r;
            float mean = s_stats[row].x, rstd = s_stats[row].y;
            int col0 = cx * 4;
            float4 gg = *(const float4*)(lng + col0);
            float4 bb = *(const float4*)(lnb + col0);
            float4 v;
            v.x = (As[row][col0 + 0] - mean) * rstd * gg.x + bb.x;
            v.y = (As[row][col0 + 1] - mean) * rstd * gg.y + bb.y;
            v.z = (As[row][col0 + 2] - mean) * rstd * gg.z + bb.z;
            v.w = (As[row][col0 + 3] - mean) * rstd * gg.w + bb.w;
            *(float4*)(o + (size_t)(m0 + row) * 128 + col0) = v;
        }
    }
}

// ---------------- attention: one block per (seq, head) ----------------------
__global__ void k_attn(const float* __restrict__ QKV, float* __restrict__ ATT) {
    __shared__ __align__(16) float Qs[121 * 33];
    __shared__ __align__(16) float Ks[121 * 32];
    __shared__ __align__(16) float Vs[121 * 32];
    int s = blockIdx.x, h = blockIdx.y;
    int tid = threadIdx.x;

    const float* base = QKV + (size_t)s * N_ * 384;
    for (int idx = tid; idx < N_ * 32; idx += 128) {
        int n = idx >> 5, d = idx & 31;
        const float* tok = base + n * 384 + h * 32;
        Qs[n * 33 + d] = tok[d];
        Ks[n * 32 + d] = tok[128 + d];
        Vs[n * 32 + d] = tok[256 + d];
    }
    __syncthreads();

    if (tid < N_) {
        const float4* K4 = (const float4*)Ks;
        const float4* V4 = (const float4*)Vs;
        float q[32];
        #pragma unroll
        for (int d = 0; d < 32; d++) q[d] = Qs[tid * 33 + d] * 0.1767766953f;

        // pass 1: online max + sum of exp
        float mx = -1e30f, sum = 0.f;
        for (int j = 0; j < N_; j++) {
            float dot = 0.f;
            #pragma unroll
            for (int c = 0; c < 8; c++) {
                float4 k4 = K4[j * 8 + c];
                dot += q[c*4+0]*k4.x + q[c*4+1]*k4.y + q[c*4+2]*k4.z + q[c*4+3]*k4.w;
            }
            float nm = fmaxf(mx, dot);
            sum = sum * __expf(mx - nm) + __expf(dot - nm);
            mx = nm;
        }
        float inv = 1.f / sum;

        // pass 2: accumulate P @ V
        float o[32];
        #pragma unroll
        for (int d = 0; d < 32; d++) o[d] = 0.f;
        for (int j = 0; j < N_; j++) {
            float dot = 0.f;
            #pragma unroll
            for (int c = 0; c < 8; c++) {
                float4 k4 = K4[j * 8 + c];
                dot += q[c*4+0]*k4.x + q[c*4+1]*k4.y + q[c*4+2]*k4.z + q[c*4+3]*k4.w;
            }
            float p = __expf(dot - mx) * inv;
            #pragma unroll
            for (int c = 0; c < 8; c++) {
                float4 v4 = V4[j * 8 + c];
                o[c*4+0] += p * v4.x; o[c*4+1] += p * v4.y;
                o[c*4+2] += p * v4.z; o[c*4+3] += p * v4.w;
            }
        }
        float* op = ATT + ((size_t)s * N_ + tid) * H_ + h * 32;
        #pragma unroll
        for (int d = 0; d < 32; d++) op[d] = o[d];
    }
}

// ---------------- final: reduce split-K partials + bias + LayerNorm ---------
__global__ void k_final(const float* __restrict__ YP, const float* __restrict__ b_out,
                        const float* __restrict__ g, const float* __restrict__ b,
                        float* __restrict__ out) {
    __shared__ float rs[8], rq[8];
    int s = blockIdx.x, o = threadIdx.x;   // 256 threads
    float v = b_out[o];
    #pragma unroll
    for (int p = 0; p < KSPLIT; p++)
        v += YP[((size_t)p * S_ + s) * OUT_ + o];

    float sm = v, sq = v * v;
    #pragma unroll
    for (int off = 16; off > 0; off >>= 1) {
        sm += __shfl_xor_sync(0xffffffffu, sm, off);
        sq += __shfl_xor_sync(0xffffffffu, sq, off);
    }
    int wid = o >> 5;
    if ((o & 31) == 0) { rs[wid] = sm; rq[wid] = sq; }
    __syncthreads();
    if (o == 0) {
        float ts = 0.f, tq = 0.f;
        #pragma unroll
        for (int i = 0; i < 8; i++) { ts += rs[i]; tq += rq[i]; }
        float mean = ts * (1.f / 256.f);
        float var  = tq * (1.f / 256.f) - mean * mean;
        rs[0] = mean; rq[0] = rsqrtf(var + EPS_);
    }
    __syncthreads();
    float mean = rs[0], rstd = rq[0];
    out[(size_t)s * OUT_ + o] = (v - mean) * rstd * g[o] + b[o];
}

// ---------------- host launcher ---------------------------------------------
extern "C" void kernel_launch(void* const* d_in, const int* in_sizes, int n_in,
                              void* d_out, int out_size) {
    const float* forest    = (const float*)d_in[0];
    const int*   adjacency = (const int*)  d_in[1];
    const int*   perm      = (const int*)  d_in[2];
    const float* w_in      = (const float*)d_in[3];
    const float* b_in      = (const float*)d_in[4];
    const float* qkv_w     = (const float*)d_in[5];
    const float* qkv_b     = (const float*)d_in[6];
    const float* proj_w    = (const float*)d_in[7];
    const float* proj_b    = (const float*)d_in[8];
    const float* ff1_w     = (const float*)d_in[9];
    const float* ff1_b     = (const float*)d_in[10];
    const float* ff2_w     = (const float*)d_in[11];
    const float* ff2_b     = (const float*)d_in[12];
    const float* ln1_g     = (const float*)d_in[13];
    const float* ln1_b     = (const float*)d_in[14];
    const float* ln2_g     = (const float*)d_in[15];
    const float* ln2_b     = (const float*)d_in[16];
    const float* w_out     = (const float*)d_in[17];
    const float* b_out     = (const float*)d_in[18];
    const float* lnf_g     = (const float*)d_in[19];
    const float* lnf_b     = (const float*)d_in[20];

    float *X, *QKV, *ATT, *H1, *WTQKV, *WTPROJ, *WTFF1, *WTFF2, *WTOUT, *YP;
    cudaGetSymbolAddress((void**)&X,      g_X);
    cudaGetSymbolAddress((void**)&QKV,    g_QKV);
    cudaGetSymbolAddress((void**)&ATT,    g_ATT);
    cudaGetSymbolAddress((void**)&H1,     g_H1);
    cudaGetSymbolAddress((void**)&WTQKV,  g_WTQKV);
    cudaGetSymbolAddress((void**)&WTPROJ, g_WTPROJ);
    cudaGetSymbolAddress((void**)&WTFF1,  g_WTFF1);
    cudaGetSymbolAddress((void**)&WTFF2,  g_WTFF2);
    cudaGetSymbolAddress((void**)&WTOUT,  g_WTOUT);
    cudaGetSymbolAddress((void**)&YP,     g_YP);

    // weight transposes (cheap; rerun every call for determinism)
    for (int i = 0; i < 2; i++) {
        k_transpose<<<(384 * 128 + 255) / 256, 256>>>(qkv_w + i * 384 * 128,
                                                      WTQKV + i * 128 * 384, 384, 128);
        k_transpose<<<(128 * 128 + 255) / 256, 256>>>(proj_w + i * 128 * 128,
                                                      WTPROJ + i * 128 * 128, 128, 128);
        k_transpose<<<(128 * 128 + 255) / 256, 256>>>(ff1_w + i * 128 * 128,
                                                      WTFF1 + i * 128 * 128, 128, 128);
        k_transpose<<<(128 * 128 + 255) / 256, 256>>>(ff2_w + i * 128 * 128,
                                                      WTFF2 + i * 128 * 128, 128, 128);
    }
    k_transpose<<<(OUT_ * NH_ + 255) / 256, 256>>>(w_out, WTOUT, OUT_, NH_);

    // embed + PE + permute
    k_embed<<<dim3(N_, S_), 128>>>(forest, adjacency, perm, w_in, b_in, X);

    for (int i = 0; i < 2; i++) {
        // QKV projection: [SN,128] x [128,384]
        k_gemm16<3, 0><<<dim3(SN_ / 16, 1), 128>>>(
            X, WTQKV + i * 128 * 384, qkv_b + i * 384,
            nullptr, nullptr, nullptr, QKV, 128, 384, 1, 0);
        // attention
        k_attn<<<dim3(S_, HEADS_), 128>>>(QKV, ATT);
        // proj + residual + LN1
        k_gemm16<1, 2><<<dim3(SN_ / 16, 1), 128>>>(
            ATT, WTPROJ + i * 128 * 128, proj_b + i * 128,
            X, ln1_g + i * 128, ln1_b + i * 128, X, 128, 128, 1, 0);
        // ff1 + relu
        k_gemm16<1, 1><<<dim3(SN_ / 16, 1), 128>>>(
            X, WTFF1 + i * 128 * 128, ff1_b + i * 128,
            nullptr, nullptr, nullptr, H1, 128, 128, 1, 0);
        // ff2 + residual + LN2
        k_gemm16<1, 2><<<dim3(SN_ / 16, 1), 128>>>(
            H1, WTFF2 + i * 128 * 128, ff2_b + i * 128,
            X, ln2_g + i * 128, ln2_b + i * 128, X, 128, 128, 1, 0);
    }

    // output projection with 16-way split-K into partials
    k_gemm16<2, 0><<<dim3(S_ / 16, KSPLIT), 128>>>(
        X, WTOUT, nullptr, nullptr, nullptr, nullptr,
        YP, NH_, OUT_, NH_ / 128, S_ * OUT_);

    // reduce partials + bias + final LN
    k_final<<<S_, OUT_>>>(YP, b_out, lnf_g, lnf_b, (float*)d_out);
}

// round 2
// speedup vs baseline: 1.2194x; 1.2194x over previous
#include <cuda_runtime.h>
#include <math.h>

#define S_     2048        // B*A
#define N_     121
#define H_     128
#define HEADS_ 4
#define OUT_   256
#define NH_    (N_*H_)     // 15488
#define SN_    (S_*N_)     // 247808
#define KSPLIT 8
#define EPS_   1e-5f
#define KC     16          // GEMM k-chunk

// ---------------- scratch (device globals; no allocations allowed) ----------
__device__ float g_X[SN_*H_];
__device__ float g_QKV[SN_*384];
__device__ float g_ATT[SN_*H_];
__device__ float g_H1[SN_*H_];
__device__ float g_WTQKV[2*128*384];
__device__ float g_WTPROJ[2*128*128];
__device__ float g_WTFF1[2*128*128];
__device__ float g_WTFF2[2*128*128];
__device__ float g_WTOUT[NH_*OUT_];        // [15488][256]
__device__ float g_YP[KSPLIT*S_*OUT_];     // split-K partials

// ---------------- fused transpose of all small weights ----------------------
// qkv_w [2][384][128] -> WTQKV [2][128][384]; proj/ff1/ff2 [2][128][128] -> [2][128][128]^T
__global__ void k_transpose_small(const float* __restrict__ qkv_w,
                                  const float* __restrict__ proj_w,
                                  const float* __restrict__ ff1_w,
                                  const float* __restrict__ ff2_w,
                                  float* __restrict__ wtqkv, float* __restrict__ wtproj,
                                  float* __restrict__ wtff1, float* __restrict__ wtff2) {
    int idx = blockIdx.x * blockDim.x + threadIdx.x;
    if (idx < 98304) {                       // qkv: 2 x 384 x 128
        int l = idx / 49152, r = idx % 49152;
        int o = r / 128, k = r % 128;
        wtqkv[l * 49152 + k * 384 + o] = qkv_w[idx];
        return;
    }
    int j = idx - 98304;
    if (j >= 98304) return;                  // proj+ff1+ff2: 3 x 32768
    int seg = j / 32768, r = j % 32768;
    int l = r / 16384, rr = r % 16384;
    int o = rr / 128, k = rr % 128;
    const float* src = (seg == 0) ? proj_w : (seg == 1) ? ff1_w : ff2_w;
    float*       dst = (seg == 0) ? wtproj : (seg == 1) ? wtff1 : wtff2;
    dst[l * 16384 + k * 128 + o] = src[r];
}

// ---------------- tiled transpose for w_out [256][15488] -> [15488][256] ----
__global__ void k_transT(const float* __restrict__ in, float* __restrict__ out,
                         int R, int C) {
    __shared__ float t[32][33];
    int c0 = blockIdx.x * 32, r0 = blockIdx.y * 32;
    int x = threadIdx.x, y = threadIdx.y;           // (32, 8)
    #pragma unroll
    for (int j = 0; j < 4; j++) {
        int r = r0 + y + j * 8;
        if (r < R && c0 + x < C) t[y + j * 8][x] = in[(size_t)r * C + c0 + x];
    }
    __syncthreads();
    #pragma unroll
    for (int j = 0; j < 4; j++) {
        int c = c0 + y + j * 8;
        if (c < C && r0 + x < R) out[(size_t)c * R + r0 + x] = t[x][y + j * 8];
    }
}

// ---------------- embed + tree PE + permutation -----------------------------
__global__ void k_embed(const float* __restrict__ forest, const int* __restrict__ adj,
                        const int* __restrict__ perm, const float* __restrict__ w_in,
                        const float* __restrict__ b_in, float* __restrict__ X) {
    int i = blockIdx.x, s = blockIdx.y, h = threadIdx.x;
    int n = perm[i];

    unsigned mask = 0;
    int cur = n;
    #pragma unroll 4
    for (int it = 0; it < 4; it++) {
        if (cur > 0) {
            int l = (cur < 4) ? 1 : (cur < 13) ? 2 : (cur < 40) ? 3 : 4;
            const int* e = adj + ((size_t)s * (N_ - 1) + (cur - 1)) * 3;
            mask |= 1u << ((l - 1) * 3 + e[2]);
            cur = e[0];
        }
    }
    const float* f = forest + ((size_t)s * N_ + n) * 12;
    float acc = b_in[h];
    #pragma unroll
    for (int k = 0; k < 12; k++) acc += f[k] * w_in[h * 12 + k];
    if (h < 12 && ((mask >> h) & 1u)) acc += 1.0f;
    X[((size_t)s * N_ + i) * H_ + h] = acc;
}

// ---------------- 128x128 tile GEMM, 8x8 micro-tiles, fused epilogues -------
// MODE 0: +bias   1: +bias+relu   2: +bias+resid+LayerNorm (Nld==128)
// MODE 3: raw partial (split-K; out offset by blockIdx.z * outStride)
template<int MODE>
__global__ void __launch_bounds__(256, 2)
k_gemm(const float* __restrict__ A, const float* __restrict__ BT,
       const float* __restrict__ bias, const float* __restrict__ resid,
       const float* __restrict__ lng, const float* __restrict__ lnb,
       float* __restrict__ out, int K, int Nld, int outStride) {
    __shared__ float As[KC][132];     // transposed A-tile [k][m]
    __shared__ float Bs[KC][128];     // [k][n]

    int tid = threadIdx.x;
    int tx = tid & 15, ty = tid >> 4;
    int m0 = blockIdx.x * 128;
    int col0 = blockIdx.y * 128;

    int nchunks = K / KC;
    int c0 = (int)((long long)nchunks * blockIdx.z / gridDim.z);
    int c1 = (int)((long long)nchunks * (blockIdx.z + 1) / gridDim.z);
    float* o = out + (size_t)blockIdx.z * outStride;

    float acc[8][8];
    #pragma unroll
    for (int r = 0; r < 8; r++)
        #pragma unroll
        for (int c = 0; c < 8; c++) acc[r][c] = 0.f;

    int ar = tid >> 2, ac = (tid & 3) * 4;          // A-load mapping
    int kr = tid >> 5, nc = (tid & 31) * 4;         // B-load mapping

    for (int t = c0; t < c1; t++) {
        __syncthreads();
        #pragma unroll
        for (int p = 0; p < 2; p++) {
            float4 v = *(const float4*)(A + (size_t)(m0 + ar + 64 * p) * K + t * KC + ac);
            As[ac + 0][ar + 64 * p] = v.x;
            As[ac + 1][ar + 64 * p] = v.y;
            As[ac + 2][ar + 64 * p] = v.z;
            As[ac + 3][ar + 64 * p] = v.w;
        }
        #pragma unroll
        for (int p = 0; p < 2; p++) {
            float4 v = *(const float4*)(BT + (size_t)(t * KC + kr + 8 * p) * Nld + col0 + nc);
            *(float4*)(&Bs[kr + 8 * p][nc]) = v;
        }
        __syncthreads();

        #pragma unroll
        for (int kk = 0; kk < KC; kk++) {
            float4 a0 = *(const float4*)(&As[kk][ty * 8]);
            float4 a1 = *(const float4*)(&As[kk][ty * 8 + 4]);
            float4 b0 = *(const float4*)(&Bs[kk][tx * 8]);
            float4 b1 = *(const float4*)(&Bs[kk][tx * 8 + 4]);
            float a[8] = {a0.x, a0.y, a0.z, a0.w, a1.x, a1.y, a1.z, a1.w};
            float b[8] = {b0.x, b0.y, b0.z, b0.w, b1.x, b1.y, b1.z, b1.w};
            #pragma unroll
            for (int r = 0; r < 8; r++)
                #pragma unroll
                for (int c = 0; c < 8; c++) acc[r][c] += a[r] * b[c];
        }
    }

    if (MODE == 3) {
        #pragma unroll
        for (int r = 0; r < 8; r++) {
            int row = m0 + ty * 8 + r;
            *(float4*)(o + (size_t)row * Nld + col0 + tx * 8)     =
                make_float4(acc[r][0], acc[r][1], acc[r][2], acc[r][3]);
            *(float4*)(o + (size_t)row * Nld + col0 + tx * 8 + 4) =
                make_float4(acc[r][4], acc[r][5], acc[r][6], acc[r][7]);
        }
        return;
    }

    float4 bi0 = *(const float4*)(bias + col0 + tx * 8);
    float4 bi1 = *(const float4*)(bias + col0 + tx * 8 + 4);
    float bi[8] = {bi0.x, bi0.y, bi0.z, bi0.w, bi1.x, bi1.y, bi1.z, bi1.w};

    if (MODE == 0 || MODE == 1) {
        #pragma unroll
        for (int r = 0; r < 8; r++) {
            int row = m0 + ty * 8 + r;
            float v[8];
            #pragma unroll
            for (int c = 0; c < 8; c++) {
                v[c] = acc[r][c] + bi[c];
                if (MODE == 1) v[c] = fmaxf(v[c], 0.f);
            }
            *(float4*)(o + (size_t)row * Nld + col0 + tx * 8)     = make_float4(v[0], v[1], v[2], v[3]);
            *(float4*)(o + (size_t)row * Nld + col0 + tx * 8 + 4) = make_float4(v[4], v[5], v[6], v[7]);
        }
    } else {
        // MODE 2: residual + LayerNorm over 128 cols (col0 == 0, Nld == 128)
        float4 g0 = *(const float4*)(lng + tx * 8), g1 = *(const float4*)(lng + tx * 8 + 4);
        float4 l0 = *(const float4*)(lnb + tx * 8), l1 = *(const float4*)(lnb + tx * 8 + 4);
        float gv[8] = {g0.x, g0.y, g0.z, g0.w, g1.x, g1.y, g1.z, g1.w};
        float lv[8] = {l0.x, l0.y, l0.z, l0.w, l1.x, l1.y, l1.z, l1.w};
        #pragma unroll
        for (int r = 0; r < 8; r++) {
            int row = m0 + ty * 8 + r;
            float4 r0 = *(const float4*)(resid + (size_t)row * 128 + tx * 8);
            float4 r1 = *(const float4*)(resid + (size_t)row * 128 + tx * 8 + 4);
            float rr[8] = {r0.x, r0.y, r0.z, r0.w, r1.x, r1.y, r1.z, r1.w};
            float v[8], sm = 0.f, sq = 0.f;
            #pragma unroll
            for (int c = 0; c < 8; c++) {
                v[c] = acc[r][c] + bi[c] + rr[c];
                sm += v[c]; sq += v[c] * v[c];
            }
            #pragma unroll
            for (int off = 8; off > 0; off >>= 1) {
                sm += __shfl_xor_sync(0xffffffffu, sm, off, 16);
                sq += __shfl_xor_sync(0xffffffffu, sq, off, 16);
            }
            float mean = sm * (1.f / 128.f);
            float rstd = rsqrtf(sq * (1.f / 128.f) - mean * mean + EPS_);
            float w[8];
            #pragma unroll
            for (int c = 0; c < 8; c++) w[c] = (v[c] - mean) * rstd * gv[c] + lv[c];
            *(float4*)(o + (size_t)row * 128 + tx * 8)     = make_float4(w[0], w[1], w[2], w[3]);
            *(float4*)(o + (size_t)row * 128 + tx * 8 + 4) = make_float4(w[4], w[5], w[6], w[7]);
        }
    }
}

// ---------------- attention: one block per (seq, head), P cached in smem ----
// dynamic smem: Ks[121*32] | Vs[121*32] | Ps[121*128]
#define ATTN_SMEM ((121*32*2 + 121*128) * 4)
__global__ void k_attn(const float* __restrict__ QKV, float* __restrict__ ATT) {
    extern __shared__ float smA[];
    float* Ks = smA;
    float* Vs = smA + 121 * 32;
    float* Ps = smA + 121 * 64;
    int s = blockIdx.x, h = blockIdx.y, tid = threadIdx.x;

    const float* base = QKV + (size_t)s * N_ * 384;
    for (int idx = tid; idx < N_ * 32; idx += 128) {
        int n = idx >> 5, d = idx & 31;
        const float* tok = base + n * 384 + h * 32;
        Ks[idx] = tok[128 + d];
        Vs[idx] = tok[256 + d];
    }
    __syncthreads();

    if (tid < N_) {
        const float4* K4 = (const float4*)Ks;
        const float4* V4 = (const float4*)Vs;
        const float4* qg = (const float4*)(base + tid * 384 + h * 32);
        float q[32];
        #pragma unroll
        for (int c = 0; c < 8; c++) {
            float4 v = qg[c];
            q[c*4+0] = v.x * 0.1767766953f; q[c*4+1] = v.y * 0.1767766953f;
            q[c*4+2] = v.z * 0.1767766953f; q[c*4+3] = v.w * 0.1767766953f;
        }

        // pass 1: dots + max (no exp)
        float mx = -1e30f;
        for (int j = 0; j < N_; j++) {
            float dot = 0.f;
            #pragma unroll
            for (int c = 0; c < 8; c++) {
                float4 k4 = K4[j * 8 + c];
                dot += q[c*4+0]*k4.x + q[c*4+1]*k4.y + q[c*4+2]*k4.z + q[c*4+3]*k4.w;
            }
            Ps[j * 128 + tid] = dot;
            mx = fmaxf(mx, dot);
        }

        // pass 2: exp + sum + PV
        float sum = 0.f, o[32];
        #pragma unroll
        for (int d = 0; d < 32; d++) o[d] = 0.f;
        for (int j = 0; j < N_; j++) {
            float p = __expf(Ps[j * 128 + tid] - mx);
            sum += p;
            #pragma unroll
            for (int c = 0; c < 8; c++) {
                float4 v4 = V4[j * 8 + c];
                o[c*4+0] += p * v4.x; o[c*4+1] += p * v4.y;
                o[c*4+2] += p * v4.z; o[c*4+3] += p * v4.w;
            }
        }
        float inv = 1.f / sum;
        float* op = ATT + ((size_t)s * N_ + tid) * H_ + h * 32;
        #pragma unroll
        for (int c = 0; c < 8; c++)
            *(float4*)(op + c * 4) = make_float4(o[c*4+0]*inv, o[c*4+1]*inv,
                                                 o[c*4+2]*inv, o[c*4+3]*inv);
    }
}

// ---------------- final: reduce split-K partials + bias + LayerNorm ---------
__global__ void k_final(const float* __restrict__ YP, const float* __restrict__ b_out,
                        const float* __restrict__ g, const float* __restrict__ b,
                        float* __restrict__ out) {
    __shared__ float rs[8], rq[8];
    int s = blockIdx.x, o = threadIdx.x;
    float v = b_out[o];
    #pragma unroll
    for (int p = 0; p < KSPLIT; p++)
        v += YP[((size_t)p * S_ + s) * OUT_ + o];

    float sm = v, sq = v * v;
    #pragma unroll
    for (int off = 16; off > 0; off >>= 1) {
        sm += __shfl_xor_sync(0xffffffffu, sm, off);
        sq += __shfl_xor_sync(0xffffffffu, sq, off);
    }
    int wid = o >> 5;
    if ((o & 31) == 0) { rs[wid] = sm; rq[wid] = sq; }
    __syncthreads();
    if (o == 0) {
        float ts = 0.f, tq = 0.f;
        #pragma unroll
        for (int i = 0; i < 8; i++) { ts += rs[i]; tq += rq[i]; }
        float mean = ts * (1.f / 256.f);
        float var  = tq * (1.f / 256.f) - mean * mean;
        rs[0] = mean; rq[0] = rsqrtf(var + EPS_);
    }
    __syncthreads();
    out[(size_t)s * OUT_ + o] = (v - rs[0]) * rq[0] * g[o] + b[o];
}

// ---------------- host launcher ---------------------------------------------
extern "C" void kernel_launch(void* const* d_in, const int* in_sizes, int n_in,
                              void* d_out, int out_size) {
    const float* forest    = (const float*)d_in[0];
    const int*   adjacency = (const int*)  d_in[1];
    const int*   perm      = (const int*)  d_in[2];
    const float* w_in      = (const float*)d_in[3];
    const float* b_in      = (const float*)d_in[4];
    const float* qkv_w     = (const float*)d_in[5];
    const float* qkv_b     = (const float*)d_in[6];
    const float* proj_w    = (const float*)d_in[7];
    const float* proj_b    = (const float*)d_in[8];
    const float* ff1_w     = (const float*)d_in[9];
    const float* ff1_b     = (const float*)d_in[10];
    const float* ff2_w     = (const float*)d_in[11];
    const float* ff2_b     = (const float*)d_in[12];
    const float* ln1_g     = (const float*)d_in[13];
    const float* ln1_b     = (const float*)d_in[14];
    const float* ln2_g     = (const float*)d_in[15];
    const float* ln2_b     = (const float*)d_in[16];
    const float* w_out     = (const float*)d_in[17];
    const float* b_out     = (const float*)d_in[18];
    const float* lnf_g     = (const float*)d_in[19];
    const float* lnf_b     = (const float*)d_in[20];

    float *X, *QKV, *ATT, *H1, *WTQKV, *WTPROJ, *WTFF1, *WTFF2, *WTOUT, *YP;
    cudaGetSymbolAddress((void**)&X,      g_X);
    cudaGetSymbolAddress((void**)&QKV,    g_QKV);
    cudaGetSymbolAddress((void**)&ATT,    g_ATT);
    cudaGetSymbolAddress((void**)&H1,     g_H1);
    cudaGetSymbolAddress((void**)&WTQKV,  g_WTQKV);
    cudaGetSymbolAddress((void**)&WTPROJ, g_WTPROJ);
    cudaGetSymbolAddress((void**)&WTFF1,  g_WTFF1);
    cudaGetSymbolAddress((void**)&WTFF2,  g_WTFF2);
    cudaGetSymbolAddress((void**)&WTOUT,  g_WTOUT);
    cudaGetSymbolAddress((void**)&YP,     g_YP);

    cudaFuncSetAttribute(k_attn, cudaFuncAttributeMaxDynamicSharedMemorySize, ATTN_SMEM);

    // launch 0: all small transposes
    k_transpose_small<<<(196608 + 255) / 256, 256>>>(qkv_w, proj_w, ff1_w, ff2_w,
                                                     WTQKV, WTPROJ, WTFF1, WTFF2);
    // launch 1: tiled transpose of w_out
    k_transT<<<dim3(NH_ / 32, OUT_ / 32), dim3(32, 8)>>>(w_out, WTOUT, OUT_, NH_);
    // launch 2: embed + PE + permute
    k_embed<<<dim3(N_, S_), 128>>>(forest, adjacency, perm, w_in, b_in, X);

    for (int i = 0; i < 2; i++) {
        // qkv projection [SN,128]x[128,384]
        k_gemm<0><<<dim3(SN_ / 128, 3, 1), 256>>>(
            X, WTQKV + i * 128 * 384, qkv_b + i * 384,
            nullptr, nullptr, nullptr, QKV, 128, 384, 0);
        // attention
        k_attn<<<dim3(S_, HEADS_), 128, ATTN_SMEM>>>(QKV, ATT);
        // proj + residual + LN1   (launch 5 on first layer -> ncu target)
        k_gemm<2><<<dim3(SN_ / 128, 1, 1), 256>>>(
            ATT, WTPROJ + i * 128 * 128, proj_b + i * 128,
            X, ln1_g + i * 128, ln1_b + i * 128, X, 128, 128, 0);
        // ff1 + relu
        k_gemm<1><<<dim3(SN_ / 128, 1, 1), 256>>>(
            X, WTFF1 + i * 128 * 128, ff1_b + i * 128,
            nullptr, nullptr, nullptr, H1, 128, 128, 0);
        // ff2 + residual + LN2
        k_gemm<2><<<dim3(SN_ / 128, 1, 1), 256>>>(
            H1, WTFF2 + i * 128 * 128, ff2_b + i * 128,
            X, ln2_g + i * 128, ln2_b + i * 128, X, 128, 128, 0);
    }

    // output projection, split-K = 8
    k_gemm<3><<<dim3(S_ / 128, OUT_ / 128, KSPLIT), 256>>>(
        X, WTOUT, nullptr, nullptr, nullptr, nullptr,
        YP, NH_, OUT_, S_ * OUT_);

    // reduce partials + bias + final LN
    k_final<<<S_, OUT_>>>(YP, b_out, lnf_g, lnf_b, (float*)d_out);
}